// round 10
// baseline (speedup 1.0000x reference)
#include <cuda_runtime.h>

#define BDIM 256

// Global scratch (no allocation allowed)
__device__ float g_flat[2048 * 162];
__device__ float g_h[2048 * 500];
__device__ float g_wbuf[3492];

// Preprocessed weights in constant memory.
// layout (floats): [0,432) W1 [9cf][48] | [432,2592) W2 [45cf][48] | [2592,3492) W3 [45cf][20]
__constant__ float4 c_w4[873];

// ---------------------------------------------------------------------------
__global__ void prep_weights_kernel(const float* __restrict__ bw1, const float* __restrict__ sw1,
                                    const float* __restrict__ bw2, const float* __restrict__ sw2,
                                    const float* __restrict__ bw3, const float* __restrict__ sw3)
{
    int tid = blockIdx.x * blockDim.x + threadIdx.x;
    for (int idx = tid; idx < 432; idx += gridDim.x * blockDim.x) {
        int cf = idx / 48, j = idx % 48;
        float v = 0.0f;
        if (j < 45) {
            int t = j / 5, o = j % 5;
            v = (cf == 0) ? bw1[o * 9 + t] : sw1[(o * 9 + t) * 8 + (cf - 1)];
        }
        g_wbuf[idx] = v;
    }
    for (int idx = tid; idx < 2160; idx += gridDim.x * blockDim.x) {
        int cf = idx / 48, j = idx % 48;
        float v = 0.0f;
        if (j < 45) {
            int c = cf / 9, f = cf % 9;
            int t = j / 5, o = j % 5;
            int kk = c * 9 + t;
            v = (f == 0) ? bw2[o * 45 + kk] : sw2[(o * 45 + kk) * 8 + (f - 1)];
        }
        g_wbuf[432 + idx] = v;
    }
    for (int idx = tid; idx < 900; idx += gridDim.x * blockDim.x) {
        int cf = idx / 20, j = idx % 20;
        float v = 0.0f;
        if (j < 18) {
            int c = cf / 9, f = cf % 9;
            int t = j / 2, o = j % 2;
            int kk = c * 9 + t;
            v = (f == 0) ? bw3[o * 45 + kk] : sw3[(o * 45 + kk) * 8 + (f - 1)];
        }
        g_wbuf[2592 + idx] = v;
    }
}

// ---------------------------------------------------------------------------
// phi: silu + all 8 cubic B-spline bases, branchless. base[f*stride+p].
// knots t_i = -2.2 + 0.4*i (matches reference grid).
// ---------------------------------------------------------------------------
__device__ __forceinline__ void write_phi9(float* base, int stride, int p, float x)
{
    base[p] = __fdividef(x, 1.0f + __expf(-x));

    float s  = (x + 2.2f) * 2.5f;
    float kf = floorf(s);
    int   k  = (int)kf;
    float u  = s - kf;
    float u2 = u * u, u3 = u2 * u;
    float um = 1.0f - u;
    const float c6 = 1.0f / 6.0f;
    float w0 = um * um * um * c6;
    float w1 = (3.0f * u3 - 6.0f * u2 + 4.0f) * c6;
    float w2 = (-3.0f * u3 + 3.0f * u2 + 3.0f * u + 1.0f) * c6;
    float w3 = u3 * c6;

    bool in = (k >= 0) && (k <= 10);
#pragma unroll
    for (int i = 0; i < 8; ++i) {
        int d = i - (k - 3);
        float v = 0.0f;
        v = (d == 0) ? w0 : v;
        v = (d == 1) ? w1 : v;
        v = (d == 2) ? w2 : v;
        v = (d == 3) ? w3 : v;
        base[(1 + i) * stride + p] = in ? v : 0.0f;
    }
}

// ---------------------------------------------------------------------------
// Fused conv stack: 2 images per block, each handled by an independent
// 128-thread warpgroup with its own smem region and named barrier.
// per-image smem (floats): bufA 7608 | aux 845 -> 8456; block total 16912.
// ---------------------------------------------------------------------------
#define GNB() asm volatile("bar.sync %0, 128;" :: "r"(grp + 1) : "memory")

__global__ __launch_bounds__(BDIM, 2)
void conv_stack_kernel(const float* __restrict__ x)
{
    extern __shared__ __align__(16) float dsm[];

    const int grp  = threadIdx.x >> 7;        // 0 or 1
    const int wtid = threadIdx.x & 127;

    float* bufA = dsm + grp * 8456;
    float* aux  = bufA + 7608;

    const int img = blockIdx.x * 2 + grp;
    const float* xin = x + img * 784;

    // ---- featurize input: feat1 [9][784]
    for (int p = wtid; p < 784; p += 128)
        write_phi9(bufA, 784, p, xin[p]);
    GNB();

    // ---- conv1 (9 cf, 5 out) + 2x2 maxpool -> aux = p1 [5][169]
    for (int pp = wtid; pp < 169; pp += 128) {
        int py = pp / 13, px = pp % 13;
        float a0[5] = {0,0,0,0,0}, a1[5] = {0,0,0,0,0};
        float a2[5] = {0,0,0,0,0}, a3[5] = {0,0,0,0,0};
        for (int cf = 0; cf < 9; ++cf) {
            const float* fp = bufA + cf * 784 + (2 * py) * 28 + 2 * px;
            float v[16];
#pragma unroll
            for (int r = 0; r < 4; ++r) {
                float2 t0 = *(const float2*)(fp + r * 28);
                float2 t1 = *(const float2*)(fp + r * 28 + 2);
                v[r * 4 + 0] = t0.x; v[r * 4 + 1] = t0.y;
                v[r * 4 + 2] = t1.x; v[r * 4 + 3] = t1.y;
            }
            int qb = cf * 12;
#pragma unroll
            for (int q = 0; q < 12; ++q) {
                float4 w4 = c_w4[qb + q];
                float wq[4] = {w4.x, w4.y, w4.z, w4.w};
#pragma unroll
                for (int m = 0; m < 4; ++m) {
                    int j = 4 * q + m;
                    if (j < 45) {
                        int t = j / 5, o = j % 5, ty = t / 3, tx = t % 3;
                        float wj = wq[m];
                        a0[o] = fmaf(wj, v[ty * 4 + tx],           a0[o]);
                        a1[o] = fmaf(wj, v[ty * 4 + tx + 1],       a1[o]);
                        a2[o] = fmaf(wj, v[(ty + 1) * 4 + tx],     a2[o]);
                        a3[o] = fmaf(wj, v[(ty + 1) * 4 + tx + 1], a3[o]);
                    }
                }
            }
        }
#pragma unroll
        for (int o = 0; o < 5; ++o)
            aux[o * 169 + pp] = fmaxf(fmaxf(a0[o], a1[o]), fmaxf(a2[o], a3[o]));
    }
    GNB();

    // ---- featurize pooled: feat2 [45][169]
    for (int idx = wtid; idx < 845; idx += 128) {
        int c = idx / 169, p = idx % 169;
        write_phi9(bufA + c * 9 * 169, 169, p, aux[idx]);
    }
    GNB();

    // ---- conv2 (45 cf, 5 out): 13x13 -> 11x11; point pair (t, t+61): stride-1
    if (wtid < 61) {
        int pA = wtid, pB = wtid + 61;
        bool hasB = (pB < 121);
        int yA = pA / 11, xA = pA % 11;
        int yB = pB / 11, xB = pB % 11;
        float aA[5] = {0,0,0,0,0}, aB[5] = {0,0,0,0,0};
        for (int cf = 0; cf < 45; ++cf) {
            const float* fp = bufA + cf * 169;
            const float* fA = fp + yA * 13 + xA;
            const float* fB = fp + yB * 13 + xB;
            float vA[9], vB[9];
#pragma unroll
            for (int r = 0; r < 3; ++r)
#pragma unroll
                for (int c = 0; c < 3; ++c) {
                    vA[r * 3 + c] = fA[r * 13 + c];
                    vB[r * 3 + c] = fB[r * 13 + c];
                }
            int qb = 108 + cf * 12;
#pragma unroll
            for (int q = 0; q < 12; ++q) {
                float4 w4 = c_w4[qb + q];
                float wq[4] = {w4.x, w4.y, w4.z, w4.w};
#pragma unroll
                for (int m = 0; m < 4; ++m) {
                    int j = 4 * q + m;
                    if (j < 45) {
                        int t = j / 5, o = j % 5;
                        aA[o] = fmaf(wq[m], vA[t], aA[o]);
                        aB[o] = fmaf(wq[m], vB[t], aB[o]);
                    }
                }
            }
        }
#pragma unroll
        for (int o = 0; o < 5; ++o) {
            aux[o * 121 + pA] = aA[o];
            if (hasB) aux[o * 121 + pB] = aB[o];
        }
    }
    GNB();

    // ---- featurize h2: feat3 [45][121]
    for (int idx = wtid; idx < 605; idx += 128) {
        int c = idx / 121, p = idx % 121;
        write_phi9(bufA + c * 9 * 121, 121, p, aux[idx]);
    }
    GNB();

    // ---- conv3 (45 cf, 2 out): 11x11 -> 9x9; point pair (t, t+41): stride-1
    if (wtid < 41) {
        int pA = wtid, pB = wtid + 41;
        bool hasB = (pB < 81);
        int yA = pA / 9, xA = pA % 9;
        int yB = pB / 9, xB = pB % 9;
        float aA[2] = {0, 0}, aB[2] = {0, 0};
        for (int cf = 0; cf < 45; ++cf) {
            const float* fp = bufA + cf * 121;
            const float* fA = fp + yA * 11 + xA;
            const float* fB = fp + yB * 11 + xB;
            float vA[9], vB[9];
#pragma unroll
            for (int r = 0; r < 3; ++r)
#pragma unroll
                for (int c = 0; c < 3; ++c) {
                    vA[r * 3 + c] = fA[r * 11 + c];
                    vB[r * 3 + c] = fB[r * 11 + c];
                }
            int qb = 648 + cf * 5;
#pragma unroll
            for (int q = 0; q < 5; ++q) {
                float4 w4 = c_w4[qb + q];
                float wq[4] = {w4.x, w4.y, w4.z, w4.w};
#pragma unroll
                for (int m = 0; m < 4; ++m) {
                    int j = 4 * q + m;
                    if (j < 18) {
                        int t = j / 2, o = j % 2;
                        aA[o] = fmaf(wq[m], vA[t], aA[o]);
                        aB[o] = fmaf(wq[m], vB[t], aB[o]);
                    }
                }
            }
        }
        float* outp = g_flat + img * 162;
        outp[pA] = aA[0]; outp[81 + pA] = aA[1];
        if (hasB) { outp[pB] = aB[0]; outp[81 + pB] = aB[1]; }
    }
}

// ---------------------------------------------------------------------------
// FC1: h[B,500] = relu(flat[B,162] @ w1^T + b1);  w1: [500,162]
// ---------------------------------------------------------------------------
__global__ __launch_bounds__(256)
void fc1_kernel(const float* __restrict__ w1, const float* __restrict__ b1, int B)
{
    __shared__ float Bs[64 * 163];
    const int tid = threadIdx.x;
    const int row0 = blockIdx.x * 64;
    const int col0 = blockIdx.y * 64;

    for (int idx = tid; idx < 64 * 162; idx += 256) {
        int n = idx / 162, k = idx % 162;
        int col = col0 + n;
        Bs[n * 163 + k] = (col < 500) ? w1[col * 162 + k] : 0.0f;
    }
    __syncthreads();

    const int i = tid >> 4, j = tid & 15;
    float acc[4][4];
#pragma unroll
    for (int r = 0; r < 4; ++r)
#pragma unroll
        for (int c = 0; c < 4; ++c) acc[r][c] = 0.0f;

    const float* Ap = g_flat + (row0 + i * 4) * 162;
    for (int k = 0; k < 162; ++k) {
        float a0 = Ap[k], a1 = Ap[162 + k], a2 = Ap[324 + k], a3 = Ap[486 + k];
        float b[4];
#pragma unroll
        for (int c = 0; c < 4; ++c) b[c] = Bs[(j + 16 * c) * 163 + k];
#pragma unroll
        for (int c = 0; c < 4; ++c) {
            acc[0][c] = fmaf(a0, b[c], acc[0][c]);
            acc[1][c] = fmaf(a1, b[c], acc[1][c]);
            acc[2][c] = fmaf(a2, b[c], acc[2][c]);
            acc[3][c] = fmaf(a3, b[c], acc[3][c]);
        }
    }
#pragma unroll
    for (int r = 0; r < 4; ++r)
#pragma unroll
        for (int c = 0; c < 4; ++c) {
            int col = col0 + j + 16 * c;
            if (col < 500) {
                float v = acc[r][c] + b1[col];
                g_h[(row0 + i * 4 + r) * 500 + col] = fmaxf(v, 0.0f);
            }
        }
}

// ---------------------------------------------------------------------------
// FC2: out[B,10] = h[B,500] @ w2^T + b2. One warp per row, 8 rows/block.
// w2 read directly via __ldg (L1/L2-resident), no smem staging, no barrier.
// ---------------------------------------------------------------------------
__global__ __launch_bounds__(256)
void fc2_kernel(const float* __restrict__ w2, const float* __restrict__ b2,
                float* __restrict__ out, int B)
{
    const int tid = threadIdx.x;
    const int warp = tid >> 5, lane = tid & 31;
    const int row = blockIdx.x * 8 + warp;

    float acc[10];
#pragma unroll
    for (int o = 0; o < 10; ++o) acc[o] = 0.0f;

    const float4* hv = (const float4*)(g_h + row * 500);
    const float4* wv = (const float4*)w2;           // [10][125] float4
#pragma unroll
    for (int c = 0; c < 4; ++c) {
        int i = lane + 32 * c;
        if (i < 125) {
            float4 hh = hv[i];
#pragma unroll
            for (int o = 0; o < 10; ++o) {
                float4 ww = __ldg(wv + o * 125 + i);
                acc[o] = fmaf(hh.x, ww.x, acc[o]);
                acc[o] = fmaf(hh.y, ww.y, acc[o]);
                acc[o] = fmaf(hh.z, ww.z, acc[o]);
                acc[o] = fmaf(hh.w, ww.w, acc[o]);
            }
        }
    }
#pragma unroll
    for (int o = 0; o < 10; ++o) {
#pragma unroll
        for (int off = 16; off > 0; off >>= 1)
            acc[o] += __shfl_down_sync(0xffffffffu, acc[o], off);
    }
    if (lane == 0) {
#pragma unroll
        for (int o = 0; o < 10; ++o)
            out[row * 10 + o] = acc[o] + b2[o];
    }
}

// ---------------------------------------------------------------------------
extern "C" void kernel_launch(void* const* d_in, const int* in_sizes, int n_in,
                              void* d_out, int out_size)
{
    const float* x   = (const float*)d_in[0];
    const float* bw1 = (const float*)d_in[1];
    const float* sw1 = (const float*)d_in[2];
    const float* bw2 = (const float*)d_in[3];
    const float* sw2 = (const float*)d_in[4];
    const float* bw3 = (const float*)d_in[5];
    const float* sw3 = (const float*)d_in[6];
    const float* w1  = (const float*)d_in[7];
    const float* b1  = (const float*)d_in[8];
    const float* w2  = (const float*)d_in[9];
    const float* b2  = (const float*)d_in[10];
    float* out = (float*)d_out;

    int B = in_sizes[0] / 784;
    const int SMEM_BYTES = 16912 * 4;   // 67,648 B dynamic smem (2 images)

    static bool attr_set = false;
    if (!attr_set) {
        cudaFuncSetAttribute(conv_stack_kernel,
                             cudaFuncAttributeMaxDynamicSharedMemorySize, SMEM_BYTES);
        attr_set = true;
    }

    prep_weights_kernel<<<4, 256>>>(bw1, sw1, bw2, sw2, bw3, sw3);

    void* wbuf_ptr = nullptr;
    cudaGetSymbolAddress(&wbuf_ptr, g_wbuf);
    cudaMemcpyToSymbolAsync(c_w4, wbuf_ptr, 3492 * sizeof(float), 0,
                            cudaMemcpyDeviceToDevice, 0);

    conv_stack_kernel<<<B / 2, BDIM, SMEM_BYTES>>>(x);
    fc1_kernel<<<dim3(B / 64, 8), 256>>>(w1, b1, B);
    fc2_kernel<<<B / 8, 256>>>(w2, b2, out, B);
}

// round 11
// speedup vs baseline: 1.1621x; 1.1621x over previous
#include <cuda_runtime.h>

#define BDIM 256

// Global scratch (no allocation allowed)
__device__ float g_flat[2048 * 162];
__device__ float g_h[2048 * 500];
__device__ float g_wbuf[3492];

// Preprocessed weights in constant memory.
// layout (floats): [0,432) W1 [9cf][48] | [432,2592) W2 [45cf][48] | [2592,3492) W3 [45cf][20]
__constant__ float4 c_w4[873];

// ---------------------------------------------------------------------------
__global__ void prep_weights_kernel(const float* __restrict__ bw1, const float* __restrict__ sw1,
                                    const float* __restrict__ bw2, const float* __restrict__ sw2,
                                    const float* __restrict__ bw3, const float* __restrict__ sw3)
{
    int tid = blockIdx.x * blockDim.x + threadIdx.x;
    for (int idx = tid; idx < 432; idx += gridDim.x * blockDim.x) {
        int cf = idx / 48, j = idx % 48;
        float v = 0.0f;
        if (j < 45) {
            int t = j / 5, o = j % 5;
            v = (cf == 0) ? bw1[o * 9 + t] : sw1[(o * 9 + t) * 8 + (cf - 1)];
        }
        g_wbuf[idx] = v;
    }
    for (int idx = tid; idx < 2160; idx += gridDim.x * blockDim.x) {
        int cf = idx / 48, j = idx % 48;
        float v = 0.0f;
        if (j < 45) {
            int c = cf / 9, f = cf % 9;
            int t = j / 5, o = j % 5;
            int kk = c * 9 + t;
            v = (f == 0) ? bw2[o * 45 + kk] : sw2[(o * 45 + kk) * 8 + (f - 1)];
        }
        g_wbuf[432 + idx] = v;
    }
    for (int idx = tid; idx < 900; idx += gridDim.x * blockDim.x) {
        int cf = idx / 20, j = idx % 20;
        float v = 0.0f;
        if (j < 18) {
            int c = cf / 9, f = cf % 9;
            int t = j / 2, o = j % 2;
            int kk = c * 9 + t;
            v = (f == 0) ? bw3[o * 45 + kk] : sw3[(o * 45 + kk) * 8 + (f - 1)];
        }
        g_wbuf[2592 + idx] = v;
    }
}

// ---------------------------------------------------------------------------
// phi: silu + all 8 cubic B-spline bases, branchless. base[f*stride+p].
// knots t_i = -2.2 + 0.4*i (matches reference grid).
// ---------------------------------------------------------------------------
__device__ __forceinline__ void write_phi9(float* base, int stride, int p, float x)
{
    base[p] = __fdividef(x, 1.0f + __expf(-x));

    float s  = (x + 2.2f) * 2.5f;
    float kf = floorf(s);
    int   k  = (int)kf;
    float u  = s - kf;
    float u2 = u * u, u3 = u2 * u;
    float um = 1.0f - u;
    const float c6 = 1.0f / 6.0f;
    float w0 = um * um * um * c6;
    float w1 = (3.0f * u3 - 6.0f * u2 + 4.0f) * c6;
    float w2 = (-3.0f * u3 + 3.0f * u2 + 3.0f * u + 1.0f) * c6;
    float w3 = u3 * c6;

    bool in = (k >= 0) && (k <= 10);
#pragma unroll
    for (int i = 0; i < 8; ++i) {
        int d = i - (k - 3);
        float v = 0.0f;
        v = (d == 0) ? w0 : v;
        v = (d == 1) ? w1 : v;
        v = (d == 2) ? w2 : v;
        v = (d == 3) ? w3 : v;
        base[(1 + i) * stride + p] = in ? v : 0.0f;
    }
}

// ---------------------------------------------------------------------------
// Fused conv stack (R6 form, best measured): one block (256 thr) per image.
// smem (floats): bufA 7608 | aux 845 -> 8456 floats = 33.8 KB
// ---------------------------------------------------------------------------
__global__ __launch_bounds__(BDIM, 4)
void conv_stack_kernel(const float* __restrict__ x)
{
    __shared__ __align__(16) float smem[8456];
    float* bufA = smem;
    float* aux  = smem + 7608;

    const int tid = threadIdx.x;
    const int img = blockIdx.x;
    const float* xin = x + img * 784;

    // ---- featurize input: feat1 [9][784]
    for (int p = tid; p < 784; p += BDIM)
        write_phi9(bufA, 784, p, xin[p]);
    __syncthreads();

    // ---- conv1 (9 cf, 5 out) + 2x2 maxpool -> aux = p1 [5][169]
    if (tid < 169) {
        int py = tid / 13, px = tid % 13;
        float a0[5] = {0,0,0,0,0}, a1[5] = {0,0,0,0,0};
        float a2[5] = {0,0,0,0,0}, a3[5] = {0,0,0,0,0};
        for (int cf = 0; cf < 9; ++cf) {
            const float* fp = bufA + cf * 784 + (2 * py) * 28 + 2 * px;
            float v[16];
#pragma unroll
            for (int r = 0; r < 4; ++r) {
                float2 t0 = *(const float2*)(fp + r * 28);
                float2 t1 = *(const float2*)(fp + r * 28 + 2);
                v[r * 4 + 0] = t0.x; v[r * 4 + 1] = t0.y;
                v[r * 4 + 2] = t1.x; v[r * 4 + 3] = t1.y;
            }
            int qb = cf * 12;
#pragma unroll
            for (int q = 0; q < 12; ++q) {
                float4 w4 = c_w4[qb + q];
                float wq[4] = {w4.x, w4.y, w4.z, w4.w};
#pragma unroll
                for (int m = 0; m < 4; ++m) {
                    int j = 4 * q + m;
                    if (j < 45) {
                        int t = j / 5, o = j % 5, ty = t / 3, tx = t % 3;
                        float wj = wq[m];
                        a0[o] = fmaf(wj, v[ty * 4 + tx],           a0[o]);
                        a1[o] = fmaf(wj, v[ty * 4 + tx + 1],       a1[o]);
                        a2[o] = fmaf(wj, v[(ty + 1) * 4 + tx],     a2[o]);
                        a3[o] = fmaf(wj, v[(ty + 1) * 4 + tx + 1], a3[o]);
                    }
                }
            }
        }
#pragma unroll
        for (int o = 0; o < 5; ++o)
            aux[o * 169 + tid] = fmaxf(fmaxf(a0[o], a1[o]), fmaxf(a2[o], a3[o]));
    }
    __syncthreads();

    // ---- featurize pooled: feat2 [45][169]
    for (int idx = tid; idx < 845; idx += BDIM) {
        int c = idx / 169, p = idx % 169;
        write_phi9(bufA + c * 9 * 169, 169, p, aux[idx]);
    }
    __syncthreads();

    // ---- conv2 (45 cf, 5 out): 13x13 -> 11x11; point pair (t, t+61): stride-1
    if (tid < 61) {
        int pA = tid, pB = tid + 61;
        bool hasB = (pB < 121);
        int yA = pA / 11, xA = pA % 11;
        int yB = pB / 11, xB = pB % 11;
        float aA[5] = {0,0,0,0,0}, aB[5] = {0,0,0,0,0};
        for (int cf = 0; cf < 45; ++cf) {
            const float* fp = bufA + cf * 169;
            const float* fA = fp + yA * 13 + xA;
            const float* fB = fp + yB * 13 + xB;
            float vA[9], vB[9];
#pragma unroll
            for (int r = 0; r < 3; ++r)
#pragma unroll
                for (int c = 0; c < 3; ++c) {
                    vA[r * 3 + c] = fA[r * 13 + c];
                    vB[r * 3 + c] = fB[r * 13 + c];
                }
            int qb = 108 + cf * 12;
#pragma unroll
            for (int q = 0; q < 12; ++q) {
                float4 w4 = c_w4[qb + q];
                float wq[4] = {w4.x, w4.y, w4.z, w4.w};
#pragma unroll
                for (int m = 0; m < 4; ++m) {
                    int j = 4 * q + m;
                    if (j < 45) {
                        int t = j / 5, o = j % 5;
                        aA[o] = fmaf(wq[m], vA[t], aA[o]);
                        aB[o] = fmaf(wq[m], vB[t], aB[o]);
                    }
                }
            }
        }
#pragma unroll
        for (int o = 0; o < 5; ++o) {
            aux[o * 121 + pA] = aA[o];
            if (hasB) aux[o * 121 + pB] = aB[o];
        }
    }
    __syncthreads();

    // ---- featurize h2: feat3 [45][121]
    for (int idx = tid; idx < 605; idx += BDIM) {
        int c = idx / 121, p = idx % 121;
        write_phi9(bufA + c * 9 * 121, 121, p, aux[idx]);
    }
    __syncthreads();

    // ---- conv3 (45 cf, 2 out): 11x11 -> 9x9; point pair (t, t+41): stride-1
    if (tid < 41) {
        int pA = tid, pB = tid + 41;
        bool hasB = (pB < 81);
        int yA = pA / 9, xA = pA % 9;
        int yB = pB / 9, xB = pB % 9;
        float aA[2] = {0, 0}, aB[2] = {0, 0};
        for (int cf = 0; cf < 45; ++cf) {
            const float* fp = bufA + cf * 121;
            const float* fA = fp + yA * 11 + xA;
            const float* fB = fp + yB * 11 + xB;
            float vA[9], vB[9];
#pragma unroll
            for (int r = 0; r < 3; ++r)
#pragma unroll
                for (int c = 0; c < 3; ++c) {
                    vA[r * 3 + c] = fA[r * 11 + c];
                    vB[r * 3 + c] = fB[r * 11 + c];
                }
            int qb = 648 + cf * 5;
#pragma unroll
            for (int q = 0; q < 5; ++q) {
                float4 w4 = c_w4[qb + q];
                float wq[4] = {w4.x, w4.y, w4.z, w4.w};
#pragma unroll
                for (int m = 0; m < 4; ++m) {
                    int j = 4 * q + m;
                    if (j < 18) {
                        int t = j / 2, o = j % 2;
                        aA[o] = fmaf(wq[m], vA[t], aA[o]);
                        aB[o] = fmaf(wq[m], vB[t], aB[o]);
                    }
                }
            }
        }
        float* outp = g_flat + img * 162;
        outp[pA] = aA[0]; outp[81 + pA] = aA[1];
        if (hasB) { outp[pB] = aB[0]; outp[81 + pB] = aB[1]; }
    }
}

// ---------------------------------------------------------------------------
// FC1: h[B,500] = relu(flat[B,162] @ w1^T + b1);  w1: [500,162]
// ---------------------------------------------------------------------------
__global__ __launch_bounds__(256)
void fc1_kernel(const float* __restrict__ w1, const float* __restrict__ b1, int B)
{
    __shared__ float Bs[64 * 163];
    const int tid = threadIdx.x;
    const int row0 = blockIdx.x * 64;
    const int col0 = blockIdx.y * 64;

    for (int idx = tid; idx < 64 * 162; idx += 256) {
        int n = idx / 162, k = idx % 162;
        int col = col0 + n;
        Bs[n * 163 + k] = (col < 500) ? w1[col * 162 + k] : 0.0f;
    }
    __syncthreads();

    const int i = tid >> 4, j = tid & 15;
    float acc[4][4];
#pragma unroll
    for (int r = 0; r < 4; ++r)
#pragma unroll
        for (int c = 0; c < 4; ++c) acc[r][c] = 0.0f;

    const float* Ap = g_flat + (row0 + i * 4) * 162;
    for (int k = 0; k < 162; ++k) {
        float a0 = Ap[k], a1 = Ap[162 + k], a2 = Ap[324 + k], a3 = Ap[486 + k];
        float b[4];
#pragma unroll
        for (int c = 0; c < 4; ++c) b[c] = Bs[(j + 16 * c) * 163 + k];
#pragma unroll
        for (int c = 0; c < 4; ++c) {
            acc[0][c] = fmaf(a0, b[c], acc[0][c]);
            acc[1][c] = fmaf(a1, b[c], acc[1][c]);
            acc[2][c] = fmaf(a2, b[c], acc[2][c]);
            acc[3][c] = fmaf(a3, b[c], acc[3][c]);
        }
    }
#pragma unroll
    for (int r = 0; r < 4; ++r)
#pragma unroll
        for (int c = 0; c < 4; ++c) {
            int col = col0 + j + 16 * c;
            if (col < 500) {
                float v = acc[r][c] + b1[col];
                g_h[(row0 + i * 4 + r) * 500 + col] = fmaxf(v, 0.0f);
            }
        }
}

// ---------------------------------------------------------------------------
// FC2: out[B,10] = h[B,500] @ w2^T + b2. One warp per row, 8 rows/block.
// w2 read directly via __ldg (L1/L2-resident), no smem staging, no barrier.
// ---------------------------------------------------------------------------
__global__ __launch_bounds__(256)
void fc2_kernel(const float* __restrict__ w2, const float* __restrict__ b2,
                float* __restrict__ out, int B)
{
    const int tid = threadIdx.x;
    const int warp = tid >> 5, lane = tid & 31;
    const int row = blockIdx.x * 8 + warp;

    float acc[10];
#pragma unroll
    for (int o = 0; o < 10; ++o) acc[o] = 0.0f;

    const float4* hv = (const float4*)(g_h + row * 500);
    const float4* wv = (const float4*)w2;           // [10][125] float4
#pragma unroll
    for (int c = 0; c < 4; ++c) {
        int i = lane + 32 * c;
        if (i < 125) {
            float4 hh = hv[i];
#pragma unroll
            for (int o = 0; o < 10; ++o) {
                float4 ww = __ldg(wv + o * 125 + i);
                acc[o] = fmaf(hh.x, ww.x, acc[o]);
                acc[o] = fmaf(hh.y, ww.y, acc[o]);
                acc[o] = fmaf(hh.z, ww.z, acc[o]);
                acc[o] = fmaf(hh.w, ww.w, acc[o]);
            }
        }
    }
#pragma unroll
    for (int o = 0; o < 10; ++o) {
#pragma unroll
        for (int off = 16; off > 0; off >>= 1)
            acc[o] += __shfl_down_sync(0xffffffffu, acc[o], off);
    }
    if (lane == 0) {
#pragma unroll
        for (int o = 0; o < 10; ++o)
            out[row * 10 + o] = acc[o] + b2[o];
    }
}

// ---------------------------------------------------------------------------
extern "C" void kernel_launch(void* const* d_in, const int* in_sizes, int n_in,
                              void* d_out, int out_size)
{
    const float* x   = (const float*)d_in[0];
    const float* bw1 = (const float*)d_in[1];
    const float* sw1 = (const float*)d_in[2];
    const float* bw2 = (const float*)d_in[3];
    const float* sw2 = (const float*)d_in[4];
    const float* bw3 = (const float*)d_in[5];
    const float* sw3 = (const float*)d_in[6];
    const float* w1  = (const float*)d_in[7];
    const float* b1  = (const float*)d_in[8];
    const float* w2  = (const float*)d_in[9];
    const float* b2  = (const float*)d_in[10];
    float* out = (float*)d_out;

    int B = in_sizes[0] / 784;

    prep_weights_kernel<<<4, 256>>>(bw1, sw1, bw2, sw2, bw3, sw3);

    void* wbuf_ptr = nullptr;
    cudaGetSymbolAddress(&wbuf_ptr, g_wbuf);
    cudaMemcpyToSymbolAsync(c_w4, wbuf_ptr, 3492 * sizeof(float), 0,
                            cudaMemcpyDeviceToDevice, 0);

    conv_stack_kernel<<<B, BDIM>>>(x);
    fc1_kernel<<<dim3(B / 64, 8), 256>>>(w1, b1, B);
    fc2_kernel<<<B / 8, 256>>>(w2, b2, out, B);
}

// round 14
// speedup vs baseline: 1.2308x; 1.0591x over previous
#include <cuda_runtime.h>

#define BDIM 256

// Global scratch (no allocation allowed)
__device__ float g_flat[2048 * 162];
__device__ float g_h[2048 * 500];
__device__ float g_wbuf[3492];

// Preprocessed weights in constant memory.
// layout (floats): [0,432) W1 [9cf][48] | [432,2592) W2 [45cf][48] | [2592,3492) W3 [45cf][20]
__constant__ float4 c_w4[873];

// ---------------------------------------------------------------------------
__global__ void prep_weights_kernel(const float* __restrict__ bw1, const float* __restrict__ sw1,
                                    const float* __restrict__ bw2, const float* __restrict__ sw2,
                                    const float* __restrict__ bw3, const float* __restrict__ sw3)
{
    int tid = blockIdx.x * blockDim.x + threadIdx.x;
    for (int idx = tid; idx < 432; idx += gridDim.x * blockDim.x) {
        int cf = idx / 48, j = idx % 48;
        float v = 0.0f;
        if (j < 45) {
            int t = j / 5, o = j % 5;
            v = (cf == 0) ? bw1[o * 9 + t] : sw1[(o * 9 + t) * 8 + (cf - 1)];
        }
        g_wbuf[idx] = v;
    }
    for (int idx = tid; idx < 2160; idx += gridDim.x * blockDim.x) {
        int cf = idx / 48, j = idx % 48;
        float v = 0.0f;
        if (j < 45) {
            int c = cf / 9, f = cf % 9;
            int t = j / 5, o = j % 5;
            int kk = c * 9 + t;
            v = (f == 0) ? bw2[o * 45 + kk] : sw2[(o * 45 + kk) * 8 + (f - 1)];
        }
        g_wbuf[432 + idx] = v;
    }
    for (int idx = tid; idx < 900; idx += gridDim.x * blockDim.x) {
        int cf = idx / 20, j = idx % 20;
        float v = 0.0f;
        if (j < 18) {
            int c = cf / 9, f = cf % 9;
            int t = j / 2, o = j % 2;
            int kk = c * 9 + t;
            v = (f == 0) ? bw3[o * 45 + kk] : sw3[(o * 45 + kk) * 8 + (f - 1)];
        }
        g_wbuf[2592 + idx] = v;
    }
}

// ---------------------------------------------------------------------------
// phi (scatter form): silu + zero all 8 basis slots + <=4 predicated stores
// of the nonzero cubic B-spline values. base[f*stride+p].
// knots t_i = -2.2 + 0.4*i (matches reference grid).
// Slot for w0 is (k-3); w_m valid iff slot (k-3+m) in [0,7].
// ---------------------------------------------------------------------------
__device__ __forceinline__ void write_phi9(float* base, int stride, int p, float x)
{
    base[p] = __fdividef(x, 1.0f + __expf(-x));

    float s  = (x + 2.2f) * 2.5f;
    float kf = floorf(s);
    int   k  = (int)kf;
    float u  = s - kf;
    float u2 = u * u, u3 = u2 * u;
    float um = 1.0f - u;
    const float c6 = 1.0f / 6.0f;
    float w0 = um * um * um * c6;
    float w1 = (3.0f * u3 - 6.0f * u2 + 4.0f) * c6;
    float w2 = (-3.0f * u3 + 3.0f * u2 + 3.0f * u + 1.0f) * c6;
    float w3 = u3 * c6;

#pragma unroll
    for (int i = 0; i < 8; ++i)
        base[(1 + i) * stride + p] = 0.0f;

    // slot0 points at basis index (k-3), i.e. base offset (1 + k-3)*stride
    float* slot = base + (k - 2) * stride + p;
    if ((unsigned)(k - 3) <= 7u) slot[0]          = w0;
    if ((unsigned)(k - 2) <= 7u) slot[stride]     = w1;
    if ((unsigned)(k - 1) <= 7u) slot[2 * stride] = w2;
    if ((unsigned)(k    ) <= 7u) slot[3 * stride] = w3;
}

// ---------------------------------------------------------------------------
// Fused conv stack: one block (256 thr) per image.
// smem (floats): bufA 7608 | aux 845 -> 8456 floats = 33.8 KB (6 blocks/SM)
// ---------------------------------------------------------------------------
__global__ __launch_bounds__(BDIM, 6)
void conv_stack_kernel(const float* __restrict__ x)
{
    __shared__ __align__(16) float smem[8456];
    float* bufA = smem;
    float* aux  = smem + 7608;

    const int tid = threadIdx.x;
    const int img = blockIdx.x;
    const float* xin = x + img * 784;

    // ---- featurize input: feat1 [9][784]
    for (int p = tid; p < 784; p += BDIM)
        write_phi9(bufA, 784, p, xin[p]);
    __syncthreads();

    // ---- conv1 (9 cf, 5 out) + 2x2 maxpool -> aux = p1 [5][169]
    if (tid < 169) {
        int py = tid / 13, px = tid % 13;
        float a0[5] = {0,0,0,0,0}, a1[5] = {0,0,0,0,0};
        float a2[5] = {0,0,0,0,0}, a3[5] = {0,0,0,0,0};
        for (int cf = 0; cf < 9; ++cf) {
            const float* fp = bufA + cf * 784 + (2 * py) * 28 + 2 * px;
            float v[16];
#pragma unroll
            for (int r = 0; r < 4; ++r) {
                float2 t0 = *(const float2*)(fp + r * 28);
                float2 t1 = *(const float2*)(fp + r * 28 + 2);
                v[r * 4 + 0] = t0.x; v[r * 4 + 1] = t0.y;
                v[r * 4 + 2] = t1.x; v[r * 4 + 3] = t1.y;
            }
            int qb = cf * 12;
#pragma unroll
            for (int q = 0; q < 12; ++q) {
                float4 w4 = c_w4[qb + q];
                float wq[4] = {w4.x, w4.y, w4.z, w4.w};
#pragma unroll
                for (int m = 0; m < 4; ++m) {
                    int j = 4 * q + m;
                    if (j < 45) {
                        int t = j / 5, o = j % 5, ty = t / 3, tx = t % 3;
                        float wj = wq[m];
                        a0[o] = fmaf(wj, v[ty * 4 + tx],           a0[o]);
                        a1[o] = fmaf(wj, v[ty * 4 + tx + 1],       a1[o]);
                        a2[o] = fmaf(wj, v[(ty + 1) * 4 + tx],     a2[o]);
                        a3[o] = fmaf(wj, v[(ty + 1) * 4 + tx + 1], a3[o]);
                    }
                }
            }
        }
#pragma unroll
        for (int o = 0; o < 5; ++o)
            aux[o * 169 + tid] = fmaxf(fmaxf(a0[o], a1[o]), fmaxf(a2[o], a3[o]));
    }
    __syncthreads();

    // ---- featurize pooled: feat2 [45][169]
    for (int idx = tid; idx < 845; idx += BDIM) {
        int c = idx / 169, p = idx % 169;
        write_phi9(bufA + c * 9 * 169, 169, p, aux[idx]);
    }
    __syncthreads();

    // ---- conv2 (45 cf, 5 out): 13x13 -> 11x11; point pair (t, t+61): stride-1
    if (tid < 61) {
        int pA = tid, pB = tid + 61;
        bool hasB = (pB < 121);
        int yA = pA / 11, xA = pA % 11;
        int yB = pB / 11, xB = pB % 11;
        float aA[5] = {0,0,0,0,0}, aB[5] = {0,0,0,0,0};
        for (int cf = 0; cf < 45; ++cf) {
            const float* fp = bufA + cf * 169;
            const float* fA = fp + yA * 13 + xA;
            const float* fB = fp + yB * 13 + xB;
            float vA[9], vB[9];
#pragma unroll
            for (int r = 0; r < 3; ++r)
#pragma unroll
                for (int c = 0; c < 3; ++c) {
                    vA[r * 3 + c] = fA[r * 13 + c];
                    vB[r * 3 + c] = fB[r * 13 + c];
                }
            int qb = 108 + cf * 12;
#pragma unroll
            for (int q = 0; q < 12; ++q) {
                float4 w4 = c_w4[qb + q];
                float wq[4] = {w4.x, w4.y, w4.z, w4.w};
#pragma unroll
                for (int m = 0; m < 4; ++m) {
                    int j = 4 * q + m;
                    if (j < 45) {
                        int t = j / 5, o = j % 5;
                        aA[o] = fmaf(wq[m], vA[t], aA[o]);
                        aB[o] = fmaf(wq[m], vB[t], aB[o]);
                    }
                }
            }
        }
#pragma unroll
        for (int o = 0; o < 5; ++o) {
            aux[o * 121 + pA] = aA[o];
            if (hasB) aux[o * 121 + pB] = aB[o];
        }
    }
    __syncthreads();

    // ---- featurize h2: feat3 [45][121]
    for (int idx = tid; idx < 605; idx += BDIM) {
        int c = idx / 121, p = idx % 121;
        write_phi9(bufA + c * 9 * 121, 121, p, aux[idx]);
    }
    __syncthreads();

    // ---- conv3 (45 cf, 2 out): 11x11 -> 9x9; point pair (t, t+41): stride-1
    if (tid < 41) {
        int pA = tid, pB = tid + 41;
        bool hasB = (pB < 81);
        int yA = pA / 9, xA = pA % 9;
        int yB = pB / 9, xB = pB % 9;
        float aA[2] = {0, 0}, aB[2] = {0, 0};
        for (int cf = 0; cf < 45; ++cf) {
            const float* fp = bufA + cf * 121;
            const float* fA = fp + yA * 11 + xA;
            const float* fB = fp + yB * 11 + xB;
            float vA[9], vB[9];
#pragma unroll
            for (int r = 0; r < 3; ++r)
#pragma unroll
                for (int c = 0; c < 3; ++c) {
                    vA[r * 3 + c] = fA[r * 11 + c];
                    vB[r * 3 + c] = fB[r * 11 + c];
                }
            int qb = 648 + cf * 5;
#pragma unroll
            for (int q = 0; q < 5; ++q) {
                float4 w4 = c_w4[qb + q];
                float wq[4] = {w4.x, w4.y, w4.z, w4.w};
#pragma unroll
                for (int m = 0; m < 4; ++m) {
                    int j = 4 * q + m;
                    if (j < 18) {
                        int t = j / 2, o = j % 2;
                        aA[o] = fmaf(wq[m], vA[t], aA[o]);
                        aB[o] = fmaf(wq[m], vB[t], aB[o]);
                    }
                }
            }
        }
        float* outp = g_flat + img * 162;
        outp[pA] = aA[0]; outp[81 + pA] = aA[1];
        if (hasB) { outp[pB] = aB[0]; outp[81 + pB] = aB[1]; }
    }
}

// ---------------------------------------------------------------------------
// FC1: h[B,500] = relu(flat[B,162] @ w1^T + b1);  w1: [500,162]
// ---------------------------------------------------------------------------
__global__ __launch_bounds__(256)
void fc1_kernel(const float* __restrict__ w1, const float* __restrict__ b1, int B)
{
    __shared__ float Bs[64 * 163];
    const int tid = threadIdx.x;
    const int row0 = blockIdx.x * 64;
    const int col0 = blockIdx.y * 64;

    for (int idx = tid; idx < 64 * 162; idx += 256) {
        int n = idx / 162, k = idx % 162;
        int col = col0 + n;
        Bs[n * 163 + k] = (col < 500) ? w1[col * 162 + k] : 0.0f;
    }
    __syncthreads();

    const int i = tid >> 4, j = tid & 15;
    float acc[4][4];
#pragma unroll
    for (int r = 0; r < 4; ++r)
#pragma unroll
        for (int c = 0; c < 4; ++c) acc[r][c] = 0.0f;

    const float* Ap = g_flat + (row0 + i * 4) * 162;
    for (int k = 0; k < 162; ++k) {
        float a0 = Ap[k], a1 = Ap[162 + k], a2 = Ap[324 + k], a3 = Ap[486 + k];
        float b[4];
#pragma unroll
        for (int c = 0; c < 4; ++c) b[c] = Bs[(j + 16 * c) * 163 + k];
#pragma unroll
        for (int c = 0; c < 4; ++c) {
            acc[0][c] = fmaf(a0, b[c], acc[0][c]);
            acc[1][c] = fmaf(a1, b[c], acc[1][c]);
            acc[2][c] = fmaf(a2, b[c], acc[2][c]);
            acc[3][c] = fmaf(a3, b[c], acc[3][c]);
        }
    }
#pragma unroll
    for (int r = 0; r < 4; ++r)
#pragma unroll
        for (int c = 0; c < 4; ++c) {
            int col = col0 + j + 16 * c;
            if (col < 500) {
                float v = acc[r][c] + b1[col];
                g_h[(row0 + i * 4 + r) * 500 + col] = fmaxf(v, 0.0f);
            }
        }
}

// ---------------------------------------------------------------------------
// FC2: out[B,10] = h[B,500] @ w2^T + b2. One warp per row, 8 rows/block.
// ---------------------------------------------------------------------------
__global__ __launch_bounds__(256)
void fc2_kernel(const float* __restrict__ w2, const float* __restrict__ b2,
                float* __restrict__ out, int B)
{
    const int tid = threadIdx.x;
    const int warp = tid >> 5, lane = tid & 31;
    const int row = blockIdx.x * 8 + warp;

    float acc[10];
#pragma unroll
    for (int o = 0; o < 10; ++o) acc[o] = 0.0f;

    const float4* hv = (const float4*)(g_h + row * 500);
    const float4* wv = (const float4*)w2;           // [10][125] float4
#pragma unroll
    for (int c = 0; c < 4; ++c) {
        int i = lane + 32 * c;
        if (i < 125) {
            float4 hh = hv[i];
#pragma unroll
            for (int o = 0; o < 10; ++o) {
                float4 ww = __ldg(wv + o * 125 + i);
                acc[o] = fmaf(hh.x, ww.x, acc[o]);
                acc[o] = fmaf(hh.y, ww.y, acc[o]);
                acc[o] = fmaf(hh.z, ww.z, acc[o]);
                acc[o] = fmaf(hh.w, ww.w, acc[o]);
            }
        }
    }
#pragma unroll
    for (int o = 0; o < 10; ++o) {
#pragma unroll
        for (int off = 16; off > 0; off >>= 1)
            acc[o] += __shfl_down_sync(0xffffffffu, acc[o], off);
    }
    if (lane == 0) {
#pragma unroll
        for (int o = 0; o < 10; ++o)
            out[row * 10 + o] = acc[o] + b2[o];
    }
}

// ---------------------------------------------------------------------------
extern "C" void kernel_launch(void* const* d_in, const int* in_sizes, int n_in,
                              void* d_out, int out_size)
{
    const float* x   = (const float*)d_in[0];
    const float* bw1 = (const float*)d_in[1];
    const float* sw1 = (const float*)d_in[2];
    const float* bw2 = (const float*)d_in[3];
    const float* sw2 = (const float*)d_in[4];
    const float* bw3 = (const float*)d_in[5];
    const float* sw3 = (const float*)d_in[6];
    const float* w1  = (const float*)d_in[7];
    const float* b1  = (const float*)d_in[8];
    const float* w2  = (const float*)d_in[9];
    const float* b2  = (const float*)d_in[10];
    float* out = (float*)d_out;

    int B = in_sizes[0] / 784;

    prep_weights_kernel<<<4, 256>>>(bw1, sw1, bw2, sw2, bw3, sw3);

    void* wbuf_ptr = nullptr;
    cudaGetSymbolAddress(&wbuf_ptr, g_wbuf);
    cudaMemcpyToSymbolAsync(c_w4, wbuf_ptr, 3492 * sizeof(float), 0,
                            cudaMemcpyDeviceToDevice, 0);

    conv_stack_kernel<<<B, BDIM>>>(x);
    fc1_kernel<<<dim3(B / 64, 8), 256>>>(w1, b1, B);
    fc2_kernel<<<B / 8, 256>>>(w2, b2, out, B);
}